// round 14
// baseline (speedup 1.0000x reference)
#include <cuda_runtime.h>
#include <cuda_fp16.h>
#include <cstdint>
#include <cstddef>

#define B_  64
#define T_  1024
#define F_  512
#define H_  512
#define G4_ 2048   // 4H
#define NCTA 128

__device__ __half g_xT[(size_t)T_ * F_ * B_];   // inputs transposed [t][k][b] fp16 (64 MB)
__device__ __half g_hbufh[2][H_ * B_];          // h [k][b] fp16, double-buffered
__device__ unsigned g_flags[NCTA * 32];         // 1 flag per 128B line

// ---------------------------------------------------------------------------
// helpers
// ---------------------------------------------------------------------------
__device__ __forceinline__ void cp16(void* dst, const void* src)
{
    unsigned d = (unsigned)__cvta_generic_to_shared(dst);
    asm volatile("cp.async.cg.shared.global [%0], [%1], 16;" :: "r"(d), "l"(src) : "memory");
}

__device__ __forceinline__ unsigned ld_acq(const unsigned* p)
{
    unsigned v;
    asm volatile("ld.acquire.gpu.global.u32 %0, [%1];" : "=r"(v) : "l"(p) : "memory");
    return v;
}

__device__ __forceinline__ void st_rel(unsigned* p, unsigned v)
{
    asm volatile("st.release.gpu.global.u32 [%0], %1;" :: "l"(p), "r"(v) : "memory");
}

__device__ __forceinline__ void mma8(float* c,
    unsigned a0, unsigned a1, unsigned a2, unsigned a3,
    unsigned b0, unsigned b1)
{
    asm volatile(
        "mma.sync.aligned.m16n8k8.row.col.f32.tf32.tf32.f32 "
        "{%0,%1,%2,%3}, {%4,%5,%6,%7}, {%8,%9}, {%0,%1,%2,%3};"
        : "+f"(c[0]), "+f"(c[1]), "+f"(c[2]), "+f"(c[3])
        : "r"(a0), "r"(a1), "r"(a2), "r"(a3), "r"(b0), "r"(b1));
}

// ---------------------------------------------------------------------------
// Prep: transpose inputs [b][t][f] fp32 -> g_xT [t][k][b] fp16.
// grid (8 f-blocks, 1024 t), 256 threads, smem tile [64 f][64 b] (stride 72).
// ---------------------------------------------------------------------------
__global__ void __launch_bounds__(256) transpose_x(const float* __restrict__ A)
{
    __shared__ __half tile[64][72];   // row stride 144 B (16B-multiple)
    const int t  = blockIdx.y;
    const int fb = blockIdx.x * 64;
    const int tid = threadIdx.x;
    const int b = tid >> 2, seg = tid & 3;

#pragma unroll
    for (int i = 0; i < 4; i++) {
        int f = seg * 16 + i * 4;
        float4 v = *(const float4*)(A + ((size_t)(b * 1024 + t)) * 512 + fb + f);
        tile[f + 0][b] = __float2half_rn(v.x);
        tile[f + 1][b] = __float2half_rn(v.y);
        tile[f + 2][b] = __float2half_rn(v.z);
        tile[f + 3][b] = __float2half_rn(v.w);
    }
    __syncthreads();

    const int f = tid >> 2;
#pragma unroll
    for (int i = 0; i < 2; i++) {
        int sg8 = seg + i * 4;                    // 8-half segment 0..7
        uint4 val = *(const uint4*)&tile[f][sg8 * 8];
        *(uint4*)(g_xT + ((size_t)t * 512 + fb + f) * 64 + sg8 * 8) = val;
    }
}

// ---------------------------------------------------------------------------
// Fused persistent LSTM: per step t, each CTA computes BOTH
//   gates(t) = h(t) @ Wh-slice   (consumed immediately)
//   xp(t+1)  = x(t+1) @ Wx-slice (stored in smem ring, consumed next step)
// sharing one chunk pipeline ([k][b] fp16 h + x sub-tiles per chunk) and one
// register-resident B set each (tf32-hi single term). No global x_proj at all.
// Flag release happens BEFORE the xp-reduce phase (overlaps barrier latency).
// ---------------------------------------------------------------------------
#define HX_STRIDE 72                       // halves per 64-b row (+8 pad)
#define CH_HALF  (128 * HX_STRIDE)         // halves per sub-tile (h or x)
#define CHUNK_HALVES (2 * CH_HALF)         // h + x per chunk
#define SG_STRIDE 18
#define SG_WARP  (64 * SG_STRIDE)
#define RING_STRIDE 17
#define RING_SLOT (64 * RING_STRIDE)

#define LSTM_SMEM (4 * CHUNK_HALVES * 2 + 8 * SG_WARP * 4 + 2 * RING_SLOT * 4 + 64)

__global__ void __launch_bounds__(256, 1) lstm_fused(
    const float* __restrict__ Wh,
    const float* __restrict__ Wx,
    const float* __restrict__ bias,
    float* __restrict__ out)
{
    extern __shared__ char smraw[];
    __half* chunks = (__half*)smraw;                                   // 4 * 36864 B
    float*  sg     = (float*)(smraw + 4 * CHUNK_HALVES * 2);           // 36864 B
    float*  ring   = (float*)(smraw + 4 * CHUNK_HALVES * 2 + 8 * SG_WARP * 4); // 8704 B
    float*  sbias  = (float*)(smraw + 4 * CHUNK_HALVES * 2 + 8 * SG_WARP * 4
                              + 2 * RING_SLOT * 4);                    // 64 B

    const int tid = threadIdx.x;
    const int cta = blockIdx.x;
    const int warp = tid >> 5, lane = tid & 31;
    const int r = lane >> 2, cq = lane & 3;

    const unsigned base = ld_acq(&g_flags[cta * 32]);

    // Preload Wh and Wx fragments (tf32 hi, single term), warp-strided ktiles.
    unsigned BH[16][2], WX[16][2];
#pragma unroll
    for (int c = 0; c < 4; c++)
#pragma unroll
        for (int j = 0; j < 2; j++) {
            int k0 = (c * 16 + j * 8 + warp) << 3;
#pragma unroll
            for (int nt = 0; nt < 2; nt++) {
                int n = nt * 8 + r;
                int col = ((n >> 2) << 9) + (cta << 2) + (n & 3);
                int bi = (c << 2) | (j << 1) | nt;
                BH[bi][0] = __float_as_uint(Wh[(size_t)(k0 + cq) * G4_ + col]);
                BH[bi][1] = __float_as_uint(Wh[(size_t)(k0 + cq + 4) * G4_ + col]);
                WX[bi][0] = __float_as_uint(Wx[(size_t)(k0 + cq) * G4_ + col]);
                WX[bi][1] = __float_as_uint(Wx[(size_t)(k0 + cq + 4) * G4_ + col]);
            }
        }

    if (tid < 16) {
        int n = tid;
        sbias[n] = bias[((n >> 2) << 9) + (cta << 2) + (n & 3)];
    }

    // zero h buffer 0
    if (tid < 128) ((unsigned*)g_hbufh[0])[cta * 128 + tid] = 0u;

    // warp-local chunk copy (h and/or x sub-tile) into dedicated buffer ch.
    auto issue_chunk = [&](const __half* hsrc, int tp, int ch, bool do_h, bool do_x) {
        __half* cb = chunks + ch * CHUNK_HALVES;
        if (do_h) {
#pragma unroll
            for (int j = 0; j < 2; j++) {
                const __half* s0 = hsrc + (size_t)(ch * 128 + j * 64 + warp * 8) * 64;
                __half* d0 = cb + (j * 64 + warp * 8) * HX_STRIDE;
#pragma unroll
                for (int i = 0; i < 2; i++) {
                    int s_ = lane + 32 * i;
                    int row8 = s_ >> 3, segc = s_ & 7;
                    cp16(d0 + row8 * HX_STRIDE + segc * 8, s0 + row8 * 64 + segc * 8);
                }
            }
        }
        if (do_x) {
            const __half* xsrc = g_xT + (size_t)tp * (512 * 64);
#pragma unroll
            for (int j = 0; j < 2; j++) {
                const __half* s0 = xsrc + (size_t)(ch * 128 + j * 64 + warp * 8) * 64;
                __half* d0 = cb + CH_HALF + (j * 64 + warp * 8) * HX_STRIDE;
#pragma unroll
                for (int i = 0; i < 2; i++) {
                    int s_ = lane + 32 * i;
                    int row8 = s_ >> 3, segc = s_ & 7;
                    cp16(d0 + row8 * HX_STRIDE + segc * 8, s0 + row8 * 64 + segc * 8);
                }
            }
        }
        asm volatile("cp.async.commit_group;" ::: "memory");
    };

    // MMA over one sub-tile of chunk ch with B-register set Bg.
    auto do_mma_sub = [&](const __half* sub, int ch, unsigned (&Bg)[16][2],
                          float (&acc)[4][2][4]) {
#pragma unroll
        for (int j = 0; j < 2; j++) {
            const int lk0 = ((j << 3) + warp) << 3;
            unsigned a[4][4];
#pragma unroll
            for (int mt = 0; mt < 4; mt++) {
                const __half* ap = sub + (lk0 + cq) * HX_STRIDE + mt * 16 + r;
                a[mt][0] = __float_as_uint(__half2float(ap[0]));
                a[mt][1] = __float_as_uint(__half2float(ap[8]));
                a[mt][2] = __float_as_uint(__half2float(ap[4 * HX_STRIDE]));
                a[mt][3] = __float_as_uint(__half2float(ap[4 * HX_STRIDE + 8]));
            }
            const int bi0 = (ch << 2) | (j << 1);
#pragma unroll
            for (int nt = 0; nt < 2; nt++)
#pragma unroll
                for (int mt = 0; mt < 4; mt++)
                    mma8(acc[mt][nt], a[mt][0], a[mt][1], a[mt][2], a[mt][3],
                         Bg[bi0 | nt][0], Bg[bi0 | nt][1]);
        }
    };

    auto store_partials = [&](float (&acc)[4][2][4]) {
        float* sgp = sg + warp * SG_WARP;
#pragma unroll
        for (int mt = 0; mt < 4; mt++) {
            int b0 = mt * 16 + r;
#pragma unroll
            for (int nt = 0; nt < 2; nt++) {
                int n = nt * 8 + cq * 2;
                *(float2*)&sgp[b0 * SG_STRIDE + n] =
                    make_float2(acc[mt][nt][0], acc[mt][nt][1]);
                *(float2*)&sgp[(b0 + 8) * SG_STRIDE + n] =
                    make_float2(acc[mt][nt][2], acc[mt][nt][3]);
            }
        }
    };

    auto ring_reduce = [&](int slot) {
#pragma unroll
        for (int i = 0; i < 4; i++) {
            int v = tid + (i << 8);
            int b = v >> 4, n = v & 15;
            float s = 0.f;
#pragma unroll
            for (int w = 0; w < 8; w++) s += sg[w * SG_WARP + b * SG_STRIDE + n];
            ring[slot * RING_SLOT + b * RING_STRIDE + n] = s;
        }
    };

    // ---- prologue: compute xp(0) into ring[0] (x-only pass) ----
    {
        issue_chunk(nullptr, 0, 0, false, true);
        issue_chunk(nullptr, 0, 1, false, true);
        issue_chunk(nullptr, 0, 2, false, true);
        issue_chunk(nullptr, 0, 3, false, true);

        float xacc[4][2][4];
#pragma unroll
        for (int mt = 0; mt < 4; mt++)
#pragma unroll
            for (int nt = 0; nt < 2; nt++)
#pragma unroll
                for (int k = 0; k < 4; k++) xacc[mt][nt][k] = 0.f;

#pragma unroll
        for (int ch = 0; ch < 4; ch++) {
            switch (ch) {
                case 0: asm volatile("cp.async.wait_group 3;" ::: "memory"); break;
                case 1: asm volatile("cp.async.wait_group 2;" ::: "memory"); break;
                case 2: asm volatile("cp.async.wait_group 1;" ::: "memory"); break;
                default: asm volatile("cp.async.wait_group 0;" ::: "memory"); break;
            }
            __syncwarp();
            do_mma_sub(chunks + ch * CHUNK_HALVES + CH_HALF, ch, WX, xacc);
        }
        store_partials(xacc);
        __syncthreads();
        ring_reduce(0);
    }

    __syncthreads();
    {   // barrier 0: init complete (h zeroed everywhere)
        unsigned tgt = base + 1;
        if (tid == 0) st_rel(&g_flags[cta * 32], tgt);
        if (tid < NCTA)
            while ((int)(ld_acq(&g_flags[tid * 32]) - tgt) < 0) {}
        __syncthreads();
    }

    const int eb = tid >> 2, ej = tid & 3;
    const int colj = (cta << 2) + ej;
    float c_reg = 0.f;

    for (int t = 0; t < T_; t++) {
        const __half* hsrc = g_hbufh[t & 1];
        const bool dx = (t + 1 < T_);

        issue_chunk(hsrc, t + 1, 0, true, dx);
        issue_chunk(hsrc, t + 1, 1, true, dx);
        issue_chunk(hsrc, t + 1, 2, true, dx);
        issue_chunk(hsrc, t + 1, 3, true, dx);

        float gacc[4][2][4], xacc[4][2][4];
#pragma unroll
        for (int mt = 0; mt < 4; mt++)
#pragma unroll
            for (int nt = 0; nt < 2; nt++)
#pragma unroll
                for (int k = 0; k < 4; k++) { gacc[mt][nt][k] = 0.f; xacc[mt][nt][k] = 0.f; }

#pragma unroll
        for (int ch = 0; ch < 4; ch++) {
            switch (ch) {
                case 0: asm volatile("cp.async.wait_group 3;" ::: "memory"); break;
                case 1: asm volatile("cp.async.wait_group 2;" ::: "memory"); break;
                case 2: asm volatile("cp.async.wait_group 1;" ::: "memory"); break;
                default: asm volatile("cp.async.wait_group 0;" ::: "memory"); break;
            }
            __syncwarp();
            const __half* cb = chunks + ch * CHUNK_HALVES;
            do_mma_sub(cb, ch, BH, gacc);
            if (dx) do_mma_sub(cb + CH_HALF, ch, WX, xacc);
        }

        store_partials(gacc);
        __syncthreads();                      // (A)

        // cell update: gates = sum8(sg) + ring[t&1] + bias
        {
            const float* rg = ring + (t & 1) * RING_SLOT;
            float v[4];
#pragma unroll
            for (int g = 0; g < 4; g++) {
                int n = (g << 2) + ej;
                float s = rg[eb * RING_STRIDE + n] + sbias[n];
#pragma unroll
                for (int w = 0; w < 8; w++) s += sg[w * SG_WARP + eb * SG_STRIDE + n];
                v[g] = s;
            }
            float si = 1.f / (1.f + __expf(-v[0]));
            float sf = 1.f / (1.f + __expf(-v[1]));
            float tg = tanhf(v[2]);
            float so = 1.f / (1.f + __expf(-v[3]));
            c_reg = sf * c_reg + si * tg;
            float hn = so * tanhf(c_reg);

            g_hbufh[(t + 1) & 1][(colj << 6) + eb] = __float2half_rn(hn);

            if (t == T_ - 1) {
                out[eb * H_ + colj]           = c_reg;   // c_fin
                out[B_ * H_ + eb * H_ + colj] = hn;      // h_fin
            }
        }
        __syncthreads();                      // (B) h stores done, sg free

        // release EARLY: barrier propagation overlaps the xp phase below
        if (tid == 0) st_rel(&g_flags[cta * 32], base + 2 + (unsigned)t);

        store_partials(xacc);
        __syncthreads();                      // (C)
        ring_reduce((t + 1) & 1);

        if (tid < NCTA) {
            unsigned tgt = base + 2 + (unsigned)t;
            while ((int)(ld_acq(&g_flags[tid * 32]) - tgt) < 0) {}
        }
        __syncthreads();                      // (D)
    }
}

// ---------------------------------------------------------------------------
extern "C" void kernel_launch(void* const* d_in, const int* in_sizes, int n_in,
                              void* d_out, int out_size)
{
    const float* inputs = (const float*)d_in[0];  // [B, T, F]
    const float* Wx     = (const float*)d_in[1];  // [F, 4H]
    const float* Wh     = (const float*)d_in[2];  // [H, 4H]
    const float* bias   = (const float*)d_in[3];  // [4H]
    float* out = (float*)d_out;                   // [2, B, H] = (c_fin, h_fin)

    (void)in_sizes; (void)n_in; (void)out_size;

    transpose_x<<<dim3(8, 1024), 256>>>(inputs);

    cudaFuncSetAttribute(lstm_fused, cudaFuncAttributeMaxDynamicSharedMemorySize, LSTM_SMEM);
    lstm_fused<<<NCTA, 256, LSTM_SMEM>>>(Wh, Wx, bias, out);
}

// round 15
// speedup vs baseline: 1.7840x; 1.7840x over previous
#include <cuda_runtime.h>
#include <cuda_fp16.h>
#include <cstdint>
#include <cstddef>

#define B_  64
#define T_  1024
#define F_  512
#define H_  512
#define G4_ 2048   // 4H
#define NCTA 128

__device__ float  g_xproj[(size_t)T_ * B_ * G4_];        // [t][b][col] fp32
__device__ __half g_hbufh[2][H_ * B_];                   // [col(k)][b] fp16, double-buffered
__device__ unsigned g_flags[NCTA * 32];                  // 1 flag per 128B line
__device__ __half g_ah[(size_t)B_ * T_ * F_];            // inputs as fp16 [m][k]
__device__ __half g_bh[(size_t)G4_ * F_];                // Wx^T fp16 [n][k]

// ---------------------------------------------------------------------------
// helpers
// ---------------------------------------------------------------------------
__device__ __forceinline__ void cp16(void* dst, const void* src)
{
    unsigned d = (unsigned)__cvta_generic_to_shared(dst);
    asm volatile("cp.async.cg.shared.global [%0], [%1], 16;" :: "r"(d), "l"(src) : "memory");
}

__device__ __forceinline__ unsigned ld_acq(const unsigned* p)
{
    unsigned v;
    asm volatile("ld.acquire.gpu.global.u32 %0, [%1];" : "=r"(v) : "l"(p) : "memory");
    return v;
}

__device__ __forceinline__ void st_rel(unsigned* p, unsigned v)
{
    asm volatile("st.release.gpu.global.u32 [%0], %1;" :: "l"(p), "r"(v) : "memory");
}

__device__ __forceinline__ unsigned pack2(float a, float b)
{
    __half2 h = __floats2half2_rn(a, b);
    return *(unsigned*)&h;
}

__device__ __forceinline__ void mma16(float* c,
    unsigned a0, unsigned a1, unsigned a2, unsigned a3,
    unsigned b0, unsigned b1)
{
    asm volatile(
        "mma.sync.aligned.m16n8k16.row.col.f32.f16.f16.f32 "
        "{%0,%1,%2,%3}, {%4,%5,%6,%7}, {%8,%9}, {%0,%1,%2,%3};"
        : "+f"(c[0]), "+f"(c[1]), "+f"(c[2]), "+f"(c[3])
        : "r"(a0), "r"(a1), "r"(a2), "r"(a3), "r"(b0), "r"(b1));
}

__device__ __forceinline__ void ldmx4(unsigned* r, unsigned addr)
{
    asm volatile(
        "ldmatrix.sync.aligned.m8n8.x4.shared.b16 {%0,%1,%2,%3}, [%4];"
        : "=r"(r[0]), "=r"(r[1]), "=r"(r[2]), "=r"(r[3]) : "r"(addr));
}

__device__ __forceinline__ void ldmx4t(unsigned* r, unsigned addr)
{
    asm volatile(
        "ldmatrix.sync.aligned.m8n8.x4.trans.shared.b16 {%0,%1,%2,%3}, [%4];"
        : "=r"(r[0]), "=r"(r[1]), "=r"(r[2]), "=r"(r[3]) : "r"(addr));
}

__device__ __forceinline__ uint32_t smem_to_u32(const void* p) {
    uint32_t a;
    asm("{ .reg .u64 t; cvta.to.shared.u64 t, %1; cvt.u32.u64 %0, t; }"
        : "=r"(a) : "l"(p));
    return a;
}

// ---------------------------------------------------------------------------
// Prep kernels: inputs -> fp16 [m][k]; Wx -> transposed fp16 [n][k]
// ---------------------------------------------------------------------------
__global__ void __launch_bounds__(256) conv_a(const float* __restrict__ A)
{
    unsigned i0 = blockIdx.x * 256 + threadIdx.x;
#pragma unroll
    for (int j = 0; j < 8; j++) {
        unsigned i = i0 + j * (8192u * 256u);
        float2 v = ((const float2*)A)[i];
        ((unsigned*)g_ah)[i] = pack2(v.x, v.y);
    }
}

__global__ void __launch_bounds__(256) conv_b(const float* __restrict__ W)
{
    unsigned i = blockIdx.x * 256 + threadIdx.x;
    int k = i >> 11, n = i & 2047;
    g_bh[(size_t)n * 512 + k] = __float2half_rn(W[i]);
}

// ---------------------------------------------------------------------------
// Kernel 1: x_proj GEMM — VERBATIM R10 (legacy fp16 mma, single B term,
// ldmatrix, 4-stage ring, occupancy 2).
// ---------------------------------------------------------------------------
#define GROW 80
#define GTILE (128 * GROW)
#define GSTAGE (2 * GTILE)
#define GHDR 1024
#define GSMEM (GHDR + 4 * GSTAGE)

__global__ void __launch_bounds__(256, 2) gemm_f16(const float* __restrict__ bias)
{
    extern __shared__ char smc[];
    const unsigned sm32 = smem_to_u32(smc);

    const int tid = threadIdx.x;
    const int n0  = blockIdx.x * 128;
    const int m0  = blockIdx.y * 128;
    const int warp = tid >> 5, lane = tid & 31;
    const int wm = warp & 1, wn = warp >> 1;
    const int r  = lane >> 2, cq = lane & 3;
    const int lr = lane & 15, lh = lane >> 4;

    float* sbias = (float*)smc;
    if (tid < 128) sbias[tid] = bias[n0 + tid];

    float acc[4][4][4];
#pragma unroll
    for (int i = 0; i < 4; i++)
#pragma unroll
        for (int j = 0; j < 4; j++)
#pragma unroll
            for (int k = 0; k < 4; k++) acc[i][j][k] = 0.f;

    auto issue = [&](int s) {
        char* base = smc + GHDR + (s & 3) * GSTAGE;
#pragma unroll
        for (int i = 0; i < 4; i++) {
            int idx  = tid + i * 256;
            int tile = idx >> 9;
            int q    = idx & 511;
            int row  = q >> 2, seg = q & 3;
            const __half* src =
                (tile == 0) ? g_ah + (size_t)(m0 + row) * 512 + s * 32 + seg * 8 :
                              g_bh + (size_t)(n0 + row) * 512 + s * 32 + seg * 8;
            cp16(base + tile * GTILE + row * GROW + seg * 16, src);
        }
        asm volatile("cp.async.commit_group;" ::: "memory");
    };

    issue(0);
    issue(1);
    issue(2);

    for (int s = 0; s < 16; s++) {
        if (s <= 13)      { asm volatile("cp.async.wait_group 2;" ::: "memory"); }
        else if (s == 14) { asm volatile("cp.async.wait_group 1;" ::: "memory"); }
        else              { asm volatile("cp.async.wait_group 0;" ::: "memory"); }
        __syncthreads();
        if (s + 3 < 16) issue(s + 3);

        const unsigned sb = sm32 + GHDR + (s & 3) * GSTAGE;
        const unsigned Aad = sb + (wm * 64 + lr) * GROW + lh * 16;
        const unsigned Bad = sb + GTILE + (wn * 32 + lr) * GROW + lh * 16;

#pragma unroll
        for (int kk = 0; kk < 2; kk++) {
            unsigned a[4][4];
#pragma unroll
            for (int mt = 0; mt < 4; mt++)
                ldmx4(a[mt], Aad + mt * 16 * GROW + kk * 32);

#pragma unroll
            for (int p = 0; p < 2; p++) {
                unsigned bq[4];
                ldmx4(bq, Bad + p * 16 * GROW + kk * 32);
#pragma unroll
                for (int mt = 0; mt < 4; mt++) {
                    mma16(acc[mt][2 * p],     a[mt][0], a[mt][1], a[mt][2], a[mt][3], bq[0], bq[2]);
                    mma16(acc[mt][2 * p + 1], a[mt][0], a[mt][1], a[mt][2], a[mt][3], bq[1], bq[3]);
                }
            }
        }
    }

    const int mbase = m0 + wm * 64;
    const int nbase = n0 + wn * 32;
#pragma unroll
    for (int nt = 0; nt < 4; nt++) {
        int nn = nbase + nt * 8 + cq * 2;
        float2 bb = *(const float2*)(sbias + nt * 8 + cq * 2 + wn * 32);
#pragma unroll
        for (int mt = 0; mt < 4; mt++) {
            int row0 = mbase + mt * 16 + r;
            int t0 = row0 & (T_ - 1), bi0 = row0 >> 10;
            float2 v0 = make_float2(acc[mt][nt][0] + bb.x, acc[mt][nt][1] + bb.y);
            *(float2*)&g_xproj[((size_t)(t0 * 64 + bi0) << 11) + nn] = v0;
            int row1 = row0 + 8;
            int t1 = row1 & (T_ - 1), bi1 = row1 >> 10;
            float2 v1 = make_float2(acc[mt][nt][2] + bb.x, acc[mt][nt][3] + bb.y);
            *(float2*)&g_xproj[((size_t)(t1 * 64 + bi1) << 11) + nn] = v1;
        }
    }
}

// ---------------------------------------------------------------------------
// Kernel 2: persistent LSTM recurrence — R13 structure, fp16 MMA datapath:
//   Wh preloaded as fp16 half2 register fragments (single term; same 11-bit
//   mantissa as tf32-hi), A fragments via ldmatrix.x4.trans on [k][b] tiles.
// Warp owns one k16-tile per chunk (k0 = 128ch + 16*warp); chunk copy mapping
// matches ownership -> consumption stays warp-local (no block syncs in loop).
// Per chunk per warp: 4 ldmatrix + 8 mma16 (was 16 LDS + 16 cvt + 16 mma8).
// ---------------------------------------------------------------------------
#define SHH_STRIDE 72                     // halves per 64-half row (+8 pad)
#define SHH_CHUNK (128 * SHH_STRIDE)      // halves per chunk
#define SG_STRIDE 18
#define SG_WARP  (64 * SG_STRIDE)

__global__ void __launch_bounds__(256, 1) lstm_kernel(
    const float* __restrict__ Wh,
    float* __restrict__ out)
{
    extern __shared__ char smraw[];
    __half* sh = (__half*)smraw;                              // 4*9216 halves = 73728 B
    float*  sg = (float*)(smraw + 4 * SHH_CHUNK * 2);         // 8*64*18 fl   = 36864 B
    float*  sx = (float*)(smraw + 4 * SHH_CHUNK * 2 + 8 * SG_WARP * 4); // 2*1024 fl

    const unsigned sh32 = smem_to_u32(sh);
    const int tid = threadIdx.x;
    const int cta = blockIdx.x;
    const int warp = tid >> 5, lane = tid & 31;
    const int r = lane >> 2, cq = lane & 3;

    const unsigned base = ld_acq(&g_flags[cta * 32]);

    // Preload Wh fragments as fp16 half2 (single term).
    // Warp owns k16-tile: k0 = c*128 + warp*16.
    // b0 = {Wh[k0+2cq], Wh[k0+2cq+1]}, b1 = {Wh[k0+2cq+8], Wh[k0+2cq+9]} (col n).
    unsigned BH[4][2][2];
#pragma unroll
    for (int c = 0; c < 4; c++) {
        int k0 = c * 128 + warp * 16;
#pragma unroll
        for (int nt = 0; nt < 2; nt++) {
            int n = nt * 8 + r;
            int col = ((n >> 2) << 9) + (cta << 2) + (n & 3);
            float w00 = Wh[(size_t)(k0 + 2 * cq)     * G4_ + col];
            float w01 = Wh[(size_t)(k0 + 2 * cq + 1) * G4_ + col];
            float w10 = Wh[(size_t)(k0 + 2 * cq + 8) * G4_ + col];
            float w11 = Wh[(size_t)(k0 + 2 * cq + 9) * G4_ + col];
            BH[c][nt][0] = pack2(w00, w01);
            BH[c][nt][1] = pack2(w10, w11);
        }
    }

    // zero h buffer 0: 32768 halves = 16384 u32, 128 per CTA
    if (tid < 128) ((unsigned*)g_hbufh[0])[cta * 128 + tid] = 0u;

    {   // load x_proj(t=0) into sx[0]
        int b = tid >> 2, g = tid & 3;
        cp16(sx + b * 16 + g * 4,
             g_xproj + ((size_t)b << 11) + ((size_t)g << 9) + (cta << 2));
        asm volatile("cp.async.commit_group;" ::: "memory");
        asm volatile("cp.async.wait_group 0;" ::: "memory");
    }

    __syncthreads();
    {   // barrier 0: init complete
        unsigned tgt = base + 1;
        if (tid == 0) st_rel(&g_flags[cta * 32], tgt);
        if (tid < NCTA)
            while ((int)(ld_acq(&g_flags[tid * 32]) - tgt) < 0) {}
        __syncthreads();
    }

    const int eb = tid >> 2, ej = tid & 3;
    const int colj = (cta << 2) + ej;
    float c_reg = 0.f;

    // ldmatrix.trans per-lane source row/col within the warp's 16-k slab:
    //   k-row = (lane&7) + ((lane>>4)<<3), b-col offset = lane&8
    const int klrow = (lane & 7) + ((lane >> 4) << 3);
    const int bcol8 = lane & 8;

    // warp-local chunk copy into DEDICATED buffer ch; warp copies exactly its
    // k16 slab: rows [warp*16, warp*16+16) of the chunk (2 KB -> 4 cp16/lane).
    auto issue_chunk = [&](const __half* hsrc, int ch) {
        const __half* s0 = hsrc + (size_t)(ch * 128 + warp * 16) * 64;
        __half* d0 = sh + ch * SHH_CHUNK + (warp * 16) * SHH_STRIDE;
#pragma unroll
        for (int i = 0; i < 4; i++) {
            int s_ = lane + 32 * i;                // 0..127
            int row = s_ >> 3, seg = s_ & 7;
            cp16(d0 + row * SHH_STRIDE + seg * 8, s0 + row * 64 + seg * 8);
        }
        asm volatile("cp.async.commit_group;" ::: "memory");
    };

    for (int t = 0; t < T_; t++) {
        const __half* hsrc = g_hbufh[t & 1];

        // groups 0..3: h chunks; group 4: x_proj(t+1) prefetch (never waited
        // inside this step)
        issue_chunk(hsrc, 0);
        issue_chunk(hsrc, 1);
        issue_chunk(hsrc, 2);
        issue_chunk(hsrc, 3);
        if (t + 1 < T_) {
            int b = tid >> 2, g = tid & 3;
            cp16(sx + ((t + 1) & 1) * 1024 + b * 16 + g * 4,
                 g_xproj + ((size_t)((t + 1) * 64 + b) << 11)
                         + ((size_t)g << 9) + (cta << 2));
        }
        asm volatile("cp.async.commit_group;" ::: "memory");

        float acc[4][2][4];
#pragma unroll
        for (int mt = 0; mt < 4; mt++)
#pragma unroll
            for (int nt = 0; nt < 2; nt++)
#pragma unroll
                for (int k = 0; k < 4; k++) acc[mt][nt][k] = 0.f;

#pragma unroll
        for (int ch = 0; ch < 4; ch++) {
            switch (ch) {   // wait only for this chunk's group (FIFO order)
                case 0: asm volatile("cp.async.wait_group 4;" ::: "memory"); break;
                case 1: asm volatile("cp.async.wait_group 3;" ::: "memory"); break;
                case 2: asm volatile("cp.async.wait_group 2;" ::: "memory"); break;
                default: asm volatile("cp.async.wait_group 1;" ::: "memory"); break;
            }
            __syncwarp();

            // base address of this lane's ldmatrix row in the warp's k16 slab
            const unsigned hb32 = sh32 +
                ((unsigned)(ch * SHH_CHUNK + (warp * 16 + klrow) * SHH_STRIDE + bcol8) << 1);

            unsigned a[4][4];
#pragma unroll
            for (int mt = 0; mt < 4; mt++)
                ldmx4t(a[mt], hb32 + (mt * 16 << 1));

#pragma unroll
            for (int nt = 0; nt < 2; nt++)
#pragma unroll
                for (int mt = 0; mt < 4; mt++)
                    mma16(acc[mt][nt], a[mt][0], a[mt][1], a[mt][2], a[mt][3],
                          BH[ch][nt][0], BH[ch][nt][1]);
        }

        {
            float* sgp = sg + warp * SG_WARP;
#pragma unroll
            for (int mt = 0; mt < 4; mt++) {
                int b0 = mt * 16 + r;
#pragma unroll
                for (int nt = 0; nt < 2; nt++) {
                    int n = nt * 8 + cq * 2;
                    *(float2*)&sgp[b0 * SG_STRIDE + n] =
                        make_float2(acc[mt][nt][0], acc[mt][nt][1]);
                    *(float2*)&sgp[(b0 + 8) * SG_STRIDE + n] =
                        make_float2(acc[mt][nt][2], acc[mt][nt][3]);
                }
            }
        }
        __syncthreads();

        {
            const float* sxb = sx + (t & 1) * 1024;
            float v[4];
#pragma unroll
            for (int g = 0; g < 4; g++) {
                int n = (g << 2) + ej;
                float s = sxb[eb * 16 + n];
#pragma unroll
                for (int w = 0; w < 8; w++) s += sg[w * SG_WARP + eb * SG_STRIDE + n];
                v[g] = s;
            }
            float si = 1.f / (1.f + __expf(-v[0]));
            float sf = 1.f / (1.f + __expf(-v[1]));
            float tg = tanhf(v[2]);
            float so = 1.f / (1.f + __expf(-v[3]));
            c_reg = sf * c_reg + si * tg;
            float hn = so * tanhf(c_reg);

            g_hbufh[(t + 1) & 1][(colj << 6) + eb] = __float2half_rn(hn);

            if (t == T_ - 1) {
                out[eb * H_ + colj]           = c_reg;   // c_fin
                out[B_ * H_ + eb * H_ + colj] = hn;      // h_fin
            }
        }

        __syncthreads();
        {
            unsigned tgt = base + 2 + (unsigned)t;
            if (tid == 0) st_rel(&g_flags[cta * 32], tgt);
            if (tid < NCTA)
                while ((int)(ld_acq(&g_flags[tid * 32]) - tgt) < 0) {}
            __syncthreads();
        }
    }
}

// ---------------------------------------------------------------------------
extern "C" void kernel_launch(void* const* d_in, const int* in_sizes, int n_in,
                              void* d_out, int out_size)
{
    const float* inputs = (const float*)d_in[0];  // [B, T, F]
    const float* Wx     = (const float*)d_in[1];  // [F, 4H]
    const float* Wh     = (const float*)d_in[2];  // [H, 4H]
    const float* bias   = (const float*)d_in[3];  // [4H]
    float* out = (float*)d_out;                   // [2, B, H] = (c_fin, h_fin)

    (void)in_sizes; (void)n_in; (void)out_size;

    conv_a<<<8192, 256>>>(inputs);
    conv_b<<<4096, 256>>>(Wx);

    cudaFuncSetAttribute(gemm_f16, cudaFuncAttributeMaxDynamicSharedMemorySize, GSMEM);
    gemm_f16<<<dim3(G4_ / 128, (B_ * T_) / 128), 256, GSMEM>>>(bias);

    const int lstm_smem = 4 * SHH_CHUNK * 2 + 8 * SG_WARP * 4 + 2 * 1024 * 4; // 118784 B
    cudaFuncSetAttribute(lstm_kernel, cudaFuncAttributeMaxDynamicSharedMemorySize, lstm_smem);
    lstm_kernel<<<NCTA, 256, lstm_smem>>>(Wh, out);
}